// round 11
// baseline (speedup 1.0000x reference)
#include <cuda_runtime.h>
#include <cuda_fp16.h>
#include <cstdint>

// Shapes (fixed): x (2048,4096) fp32, values (1024,64,64) fp32, bias (4096,),
// block_rows/cols (1024,) int32 in [0,64), out (2048,4096) fp32.
#define KDIM  4096
#define MDIM  4096
#define TTOK  2048
#define NBMAX 1024
#define MT    128            // tokens per CTA tile
#define NT    64             // out features per tile (one row block)
#define NITEMS 1024          // 64 rows x 16 slabs

// Half-block staging: K=32 per stage, row pitch 40 fp16 = 80 B (16B multiple,
// 80*r mod 128 distinct for r=0..7 -> ldmatrix conflict-free).
#define PITCHB  80
#define XB      (128 * PITCHB)        // 10240
#define VB      (64  * PITCHB)        // 5120
#define STAGE   (XB + VB)             // 15360
#define NSTG    4
#define SMEM_TOTAL (NSTG * STAGE)     // 61440 -> 3 CTAs/SM

// ---- device scratch (static globals; no allocations allowed) ----
__device__ __half g_xh[TTOK * KDIM];          // 16 MB
__device__ __half g_vh[NBMAX * 64 * 64];      // 8 MB
__device__ int g_row_list[64 * NBMAX];
__device__ int g_row_cnt[64];
__device__ int g_row_order[64];
__device__ int g_work_ctr;

// ---- PTX helpers (baseline sm_80+ features only) ----
__device__ __forceinline__ uint32_t smem_u32(const void* p) {
    uint32_t a;
    asm("{ .reg .u64 t; cvta.to.shared.u64 t, %1; cvt.u32.u64 %0, t; }" : "=r"(a) : "l"(p));
    return a;
}
__device__ __forceinline__ void cp_async16(uint32_t saddr, const void* gaddr) {
    asm volatile("cp.async.cg.shared.global [%0], [%1], 16;" :: "r"(saddr), "l"(gaddr));
}
#define CP_COMMIT() asm volatile("cp.async.commit_group;" ::: "memory")
#define CP_WAIT(n)  asm volatile("cp.async.wait_group %0;" :: "n"(n) : "memory")

__device__ __forceinline__ void ldsm_x4(uint32_t* r, uint32_t addr) {
    asm volatile("ldmatrix.sync.aligned.m8n8.x4.shared.b16 {%0,%1,%2,%3}, [%4];"
                 : "=r"(r[0]), "=r"(r[1]), "=r"(r[2]), "=r"(r[3]) : "r"(addr));
}
__device__ __forceinline__ void mma_f16(float* d, const uint32_t* a, uint32_t b0, uint32_t b1) {
    asm volatile(
        "mma.sync.aligned.m16n8k16.row.col.f32.f16.f16.f32 "
        "{%0,%1,%2,%3}, {%4,%5,%6,%7}, {%8,%9}, {%0,%1,%2,%3};"
        : "+f"(d[0]), "+f"(d[1]), "+f"(d[2]), "+f"(d[3])
        : "r"(a[0]), "r"(a[1]), "r"(a[2]), "r"(a[3]), "r"(b0), "r"(b1));
}

__device__ __forceinline__ float gelu_tanh(float v) {
    float inner = 0.7978845608f * (v + 0.044715f * v * v * v);
    return 0.5f * v * (1.0f + tanhf(inner));
}

// ---------------------------------------------------------------------------
// Pre-pass 1 (fused): fp32 -> fp16 for both x and values in one launch.
// ---------------------------------------------------------------------------
#define XBLK 2048
#define VBLK 1024
__global__ void __launch_bounds__(256) convert_all_kernel(
    const float* __restrict__ x, const float* __restrict__ values,
    int nx4, int nv4)
{
    const int b = blockIdx.x;
    const float4* s4;
    uint2* dst;
    int n4, start, stride;
    if (b < XBLK) {
        s4 = (const float4*)x; dst = (uint2*)g_xh; n4 = nx4;
        start = b * 256 + threadIdx.x; stride = XBLK * 256;
    } else {
        s4 = (const float4*)values; dst = (uint2*)g_vh; n4 = nv4;
        start = (b - XBLK) * 256 + threadIdx.x; stride = VBLK * 256;
    }
    for (int i = start; i < n4; i += stride) {
        float4 v = s4[i];
        __half2 a = __floats2half2_rn(v.x, v.y);
        __half2 c = __floats2half2_rn(v.z, v.w);
        uint2 o{*(uint32_t*)&a, *(uint32_t*)&c};
        dst[i] = o;
    }
}

// ---------------------------------------------------------------------------
// Pre-pass 2 (fused): lists + LPT order + work-counter reset, one CTA.
// ---------------------------------------------------------------------------
__global__ void __launch_bounds__(1024) lists_order_kernel(
    const int* __restrict__ brows, int nb)
{
    __shared__ int cnts[64];
    const int warp = threadIdx.x >> 5, lane = threadIdx.x & 31;
    if (threadIdx.x == 0) g_work_ctr = 0;   // reset queue every launch/replay
    for (int r = warp; r < 64; r += 32) {
        int cnt = 0;
        for (int base = 0; base < nb; base += 32) {
            int n = base + lane;
            int row = (n < nb) ? brows[n] : -1;
            unsigned m = __ballot_sync(0xFFFFFFFFu, row == r);
            if (row == r)
                g_row_list[r * NBMAX + cnt + __popc(m & ((1u << lane) - 1u))] = n;
            cnt += __popc(m);
        }
        if (lane == 0) { g_row_cnt[r] = cnt; cnts[r] = cnt; }
    }
    __syncthreads();
    const int i = threadIdx.x;
    if (i < 64) {
        const int c = cnts[i];
        int rank = 0;
        #pragma unroll
        for (int j = 0; j < 64; j++) {
            const int cj = cnts[j];
            rank += (cj > c) || (cj == c && j < i);
        }
        g_row_order[rank] = i;
    }
}

// ---------------------------------------------------------------------------
// Half-stage loader: K=32 slice of X and V into stage s. 3 cp.async/thread.
// ---------------------------------------------------------------------------
__device__ __forceinline__ void load_half(uint32_t sb, int s, int n, int c, int kh,
                                          int t0, int tid)
{
    const uint32_t xs = sb + s * STAGE;
    const uint32_t vs = xs + XB;
    const int k0 = c * 64 + kh * 32;
    #pragma unroll
    for (int i = 0; i < 2; i++) {
        const int id = tid + i * 256;
        const int row = id >> 2, cb = id & 3;
        const size_t g = (size_t)(t0 + row) * KDIM + k0 + cb * 8;
        cp_async16(xs + row * PITCHB + cb * 16, g_xh + g);
    }
    {
        const int row = tid >> 2, cb = tid & 3;
        const size_t g = (size_t)n * 4096 + row * 64 + kh * 32 + cb * 8;
        cp_async16(vs + row * PITCHB + cb * 16, g_vh + g);
    }
}

// ---------------------------------------------------------------------------
// Main kernel: persistent CTAs popping (row, slab) items off an LPT-ordered
// queue. Per item: 8 warps (4 token x 2 n), warp tile 32x32, fp16 HMMA,
// fp32 accum, 4-stage K32 cp.async pipeline. Pop order cannot affect values.
// ---------------------------------------------------------------------------
__global__ void __launch_bounds__(256, 3) fsl_hmma_kernel(
    const float* __restrict__ bias,
    const int*   __restrict__ bcols,
    float*       __restrict__ out)
{
    extern __shared__ char smem[];
    __shared__ int s_item;
    const uint32_t sb = smem_u32(smem);
    const int tid  = threadIdx.x;
    const int warp = tid >> 5;
    const int lane = tid & 31;

    const int wt = (warp >> 1) * 32;
    const int wn = (warp & 1) * 32;

    // ldmatrix lane-address components (mapping validated R4-R9)
    const int a_m = (lane & 7) + ((lane >> 3) & 1) * 8;
    const int a_k = (lane >> 4) * 8;
    const int b_n = (lane & 7) + ((lane >> 4) & 1) * 8;
    const int b_k = ((lane >> 3) & 1) * 8;

    const int row0 = lane >> 2;
    const int cp2  = (lane & 3) * 2;

    for (;;) {
        if (tid == 0) s_item = atomicAdd(&g_work_ctr, 1);
        __syncthreads();                       // broadcast item; fence smem reuse
        const int item = s_item;
        if (item >= NITEMS) break;

        const int r    = g_row_order[item >> 4];
        const int slab = item & 15;
        const int t0   = slab * MT;

        const int cnt   = g_row_cnt[r];
        const int total = 2 * cnt;
        const int* list = &g_row_list[r * NBMAX];

        float acc[2][4][4];
        #pragma unroll
        for (int mi = 0; mi < 2; mi++)
            #pragma unroll
            for (int nj = 0; nj < 4; nj++)
                #pragma unroll
                for (int q = 0; q < 4; q++) acc[mi][nj][q] = 0.0f;

        // Prologue: prime 3 of 4 stages. Stage j = block list[j>>1], half j&1.
        #pragma unroll
        for (int j = 0; j < 3; j++) {
            if (j < total) {
                const int n = list[j >> 1];
                load_half(sb, j, n, __ldg(&bcols[n]), j & 1, t0, tid);
            }
            CP_COMMIT();
        }

        for (int i = 0; i < total; i++) {
            CP_WAIT(2);
            __syncthreads();

            if (i + 3 < total) {
                const int j = i + 3;
                const int n = list[j >> 1];
                load_half(sb, (i + 3) & 3, n, __ldg(&bcols[n]), j & 1, t0, tid);
            }
            CP_COMMIT();

            const uint32_t xs = sb + (i & 3) * STAGE;
            const uint32_t vs = xs + XB;

            #pragma unroll
            for (int kc = 0; kc < 2; kc++) {
                uint32_t ah[2][4], bh[2][4];
                const uint32_t ao = (wt + a_m) * PITCHB + (kc * 16 + a_k) * 2;
                const uint32_t bo = (wn + b_n) * PITCHB + (kc * 16 + b_k) * 2;
                #pragma unroll
                for (int mi = 0; mi < 2; mi++)
                    ldsm_x4(ah[mi], xs + ao + mi * 16 * PITCHB);
                #pragma unroll
                for (int j = 0; j < 2; j++)
                    ldsm_x4(bh[j], vs + bo + j * 16 * PITCHB);
                #pragma unroll
                for (int mi = 0; mi < 2; mi++)
                    #pragma unroll
                    for (int j = 0; j < 2; j++) {
                        mma_f16(acc[mi][2 * j + 0], ah[mi], bh[j][0], bh[j][1]);
                        mma_f16(acc[mi][2 * j + 1], ah[mi], bh[j][2], bh[j][3]);
                    }
            }
        }

        // Epilogue: bias + tanh-GELU, float2 stores.
        #pragma unroll
        for (int mi = 0; mi < 2; mi++) {
            #pragma unroll
            for (int nj = 0; nj < 4; nj++) {
                const int nb = wn + nj * 8 + cp2;
                const float b0 = __ldg(&bias[r * 64 + nb]);
                const float b1 = __ldg(&bias[r * 64 + nb + 1]);
                #pragma unroll
                for (int h = 0; h < 2; h++) {
                    const int m = wt + mi * 16 + row0 + h * 8;
                    float2 o;
                    o.x = gelu_tanh(acc[mi][nj][2 * h + 0] + b0);
                    o.y = gelu_tanh(acc[mi][nj][2 * h + 1] + b1);
                    *(float2*)&out[(size_t)(t0 + m) * MDIM + r * 64 + nb] = o;
                }
            }
        }
        __syncthreads();   // all warps past smem reads before next item's loads
    }
}

// ---------------------------------------------------------------------------
extern "C" void kernel_launch(void* const* d_in, const int* in_sizes, int n_in,
                              void* d_out, int out_size)
{
    const float* x      = (const float*)d_in[0];
    const float* values = (const float*)d_in[1];
    const float* bias   = (const float*)d_in[2];
    const int*   brows  = (const int*)d_in[3];
    const int*   bcols  = (const int*)d_in[4];
    float*       out    = (float*)d_out;

    const int n_blocks = in_sizes[3];
    const int x_elems  = in_sizes[0];
    const int v_elems  = in_sizes[1];

    cudaFuncSetAttribute(fsl_hmma_kernel,
                         cudaFuncAttributeMaxDynamicSharedMemorySize, SMEM_TOTAL);

    convert_all_kernel<<<XBLK + VBLK, 256>>>(x, values, x_elems / 4, v_elems / 4);
    lists_order_kernel<<<1, 1024>>>(brows, n_blocks);

    fsl_hmma_kernel<<<444, 256, SMEM_TOTAL>>>(bias, bcols, out);   // 3 CTAs/SM persistent
}

// round 13
// speedup vs baseline: 1.0358x; 1.0358x over previous
#include <cuda_runtime.h>
#include <cuda_fp16.h>
#include <cstdint>

// Shapes (fixed): x (2048,4096) fp32, values (1024,64,64) fp32, bias (4096,),
// block_rows/cols (1024,) int32 in [0,64), out (2048,4096) fp32.
#define KDIM  4096
#define MDIM  4096
#define TTOK  2048
#define NBMAX 1024
#define MT    128            // tokens per CTA
#define NT    64             // out features per CTA (one row block)

// Half-block staging: K=32 per stage, row pitch 40 fp16 = 80 B (16B multiple,
// 80*r mod 128 distinct for r=0..7 -> ldmatrix conflict-free).
#define PITCHB  80
#define XB      (128 * PITCHB)        // 10240
#define VB      (64  * PITCHB)        // 5120
#define STAGE   (XB + VB)             // 15360
#define NSTG    4
#define SMEM_TOTAL (NSTG * STAGE)     // 61440 -> 3 CTAs/SM

// ---- device scratch (static globals; no allocations allowed) ----
__device__ __half g_xh[TTOK * KDIM];          // 16 MB
__device__ __half g_vh[NBMAX * 64 * 64];      // 8 MB
__device__ int g_row_list[64 * NBMAX];
__device__ int g_row_cnt[64];
__device__ int g_row_order[64];

// ---- PTX helpers (baseline sm_80+ features only) ----
__device__ __forceinline__ uint32_t smem_u32(const void* p) {
    uint32_t a;
    asm("{ .reg .u64 t; cvta.to.shared.u64 t, %1; cvt.u32.u64 %0, t; }" : "=r"(a) : "l"(p));
    return a;
}
__device__ __forceinline__ void cp_async16(uint32_t saddr, const void* gaddr) {
    asm volatile("cp.async.cg.shared.global [%0], [%1], 16;" :: "r"(saddr), "l"(gaddr));
}
#define CP_COMMIT() asm volatile("cp.async.commit_group;" ::: "memory")
#define CP_WAIT(n)  asm volatile("cp.async.wait_group %0;" :: "n"(n) : "memory")

__device__ __forceinline__ void ldsm_x4(uint32_t* r, uint32_t addr) {
    asm volatile("ldmatrix.sync.aligned.m8n8.x4.shared.b16 {%0,%1,%2,%3}, [%4];"
                 : "=r"(r[0]), "=r"(r[1]), "=r"(r[2]), "=r"(r[3]) : "r"(addr));
}
__device__ __forceinline__ void mma_f16(float* d, const uint32_t* a, uint32_t b0, uint32_t b1) {
    asm volatile(
        "mma.sync.aligned.m16n8k16.row.col.f32.f16.f16.f32 "
        "{%0,%1,%2,%3}, {%4,%5,%6,%7}, {%8,%9}, {%0,%1,%2,%3};"
        : "+f"(d[0]), "+f"(d[1]), "+f"(d[2]), "+f"(d[3])
        : "r"(a[0]), "r"(a[1]), "r"(a[2]), "r"(a[3]), "r"(b0), "r"(b1));
}

__device__ __forceinline__ float gelu_tanh(float v) {
    float inner = 0.7978845608f * (v + 0.044715f * v * v * v);
    return 0.5f * v * (1.0f + tanhf(inner));
}

// ---------------------------------------------------------------------------
// SINGLE fused pre-pass launch:
//   block 0:          per-row lists + LPT order (overlaps with converts)
//   blocks 1..XBLK:   x fp32 -> fp16
//   blocks XBLK+1.. : values fp32 -> fp16
// ---------------------------------------------------------------------------
#define XBLK 2048
#define VBLK 1024
__global__ void __launch_bounds__(256) prepass_kernel(
    const float* __restrict__ x, const float* __restrict__ values,
    const int* __restrict__ brows,
    int nx4, int nv4, int nb)
{
    const int b = blockIdx.x;
    if (b == 0) {
        // lists + order with 8 warps (256 threads)
        __shared__ int cnts[64];
        const int warp = threadIdx.x >> 5, lane = threadIdx.x & 31;
        for (int r = warp; r < 64; r += 8) {
            int cnt = 0;
            for (int base = 0; base < nb; base += 32) {
                int n = base + lane;
                int row = (n < nb) ? brows[n] : -1;
                unsigned m = __ballot_sync(0xFFFFFFFFu, row == r);
                if (row == r)
                    g_row_list[r * NBMAX + cnt + __popc(m & ((1u << lane) - 1u))] = n;
                cnt += __popc(m);
            }
            if (lane == 0) { g_row_cnt[r] = cnt; cnts[r] = cnt; }
        }
        __syncthreads();
        const int i = threadIdx.x;
        if (i < 64) {
            const int c = cnts[i];
            int rank = 0;
            #pragma unroll
            for (int j = 0; j < 64; j++) {
                const int cj = cnts[j];
                rank += (cj > c) || (cj == c && j < i);
            }
            g_row_order[rank] = i;
        }
        return;
    }

    const float4* s4;
    uint2* dst;
    int n4, start, stride;
    if (b <= XBLK) {
        s4 = (const float4*)x; dst = (uint2*)g_xh; n4 = nx4;
        start = (b - 1) * 256 + threadIdx.x; stride = XBLK * 256;
    } else {
        s4 = (const float4*)values; dst = (uint2*)g_vh; n4 = nv4;
        start = (b - 1 - XBLK) * 256 + threadIdx.x; stride = VBLK * 256;
    }
    for (int i = start; i < n4; i += stride) {
        float4 v = s4[i];
        __half2 a = __floats2half2_rn(v.x, v.y);
        __half2 c = __floats2half2_rn(v.z, v.w);
        uint2 o{*(uint32_t*)&a, *(uint32_t*)&c};
        dst[i] = o;
    }
}

// ---------------------------------------------------------------------------
// Half-stage loader: K=32 slice of X and V into stage s. 3 cp.async/thread.
// ---------------------------------------------------------------------------
__device__ __forceinline__ void load_half(uint32_t sb, int s, int n, int c, int kh,
                                          int t0, int tid)
{
    const uint32_t xs = sb + s * STAGE;
    const uint32_t vs = xs + XB;
    const int k0 = c * 64 + kh * 32;
    #pragma unroll
    for (int i = 0; i < 2; i++) {
        const int id = tid + i * 256;
        const int row = id >> 2, cb = id & 3;
        const size_t g = (size_t)(t0 + row) * KDIM + k0 + cb * 8;
        cp_async16(xs + row * PITCHB + cb * 16, g_xh + g);
    }
    {
        const int row = tid >> 2, cb = tid & 3;
        const size_t g = (size_t)n * 4096 + row * 64 + kh * 32 + cb * 8;
        cp_async16(vs + row * PITCHB + cb * 16, g_vh + g);
    }
}

// ---------------------------------------------------------------------------
// Main kernel (identical to the 99.1us R9 version): 256 threads = 8 warps
// (4 token x 2 n), warp tile 32x32, single-product fp16 HMMA, fp32 accum,
// 4-stage K32 cp.async pipeline, LPT row mapping via g_row_order.
// ---------------------------------------------------------------------------
__global__ void __launch_bounds__(256, 3) fsl_hmma_kernel(
    const float* __restrict__ bias,
    const int*   __restrict__ bcols,
    float*       __restrict__ out)
{
    extern __shared__ char smem[];
    const uint32_t sb = smem_u32(smem);
    const int tid  = threadIdx.x;
    const int warp = tid >> 5;
    const int lane = tid & 31;
    const int slab = blockIdx.x & 15;
    const int r    = g_row_order[blockIdx.x >> 4];
    const int t0   = slab * MT;

    const int wt = (warp >> 1) * 32;
    const int wn = (warp & 1) * 32;

    const int cnt   = g_row_cnt[r];
    const int total = 2 * cnt;                 // half-block stages
    const int* list = &g_row_list[r * NBMAX];

    float acc[2][4][4];
    #pragma unroll
    for (int mi = 0; mi < 2; mi++)
        #pragma unroll
        for (int nj = 0; nj < 4; nj++)
            #pragma unroll
            for (int q = 0; q < 4; q++) acc[mi][nj][q] = 0.0f;

    // ldmatrix lane-address components (mapping validated R4-R9)
    const int a_m = (lane & 7) + ((lane >> 3) & 1) * 8;
    const int a_k = (lane >> 4) * 8;
    const int b_n = (lane & 7) + ((lane >> 4) & 1) * 8;
    const int b_k = ((lane >> 3) & 1) * 8;

    // Prologue: prime 3 of 4 stages. Stage j = block list[j>>1], half j&1.
    #pragma unroll
    for (int j = 0; j < 3; j++) {
        if (j < total) {
            const int n = list[j >> 1];
            load_half(sb, j, n, __ldg(&bcols[n]), j & 1, t0, tid);
        }
        CP_COMMIT();
    }

    for (int i = 0; i < total; i++) {
        CP_WAIT(2);
        __syncthreads();

        // Refill the stage freed last iteration (overlaps compute)
        if (i + 3 < total) {
            const int j = i + 3;
            const int n = list[j >> 1];
            load_half(sb, (i + 3) & 3, n, __ldg(&bcols[n]), j & 1, t0, tid);
        }
        CP_COMMIT();

        const uint32_t xs = sb + (i & 3) * STAGE;
        const uint32_t vs = xs + XB;

        #pragma unroll
        for (int kc = 0; kc < 2; kc++) {
            uint32_t ah[2][4], bh[2][4];
            const uint32_t ao = (wt + a_m) * PITCHB + (kc * 16 + a_k) * 2;
            const uint32_t bo = (wn + b_n) * PITCHB + (kc * 16 + b_k) * 2;
            #pragma unroll
            for (int mi = 0; mi < 2; mi++)
                ldsm_x4(ah[mi], xs + ao + mi * 16 * PITCHB);
            #pragma unroll
            for (int j = 0; j < 2; j++)
                ldsm_x4(bh[j], vs + bo + j * 16 * PITCHB);
            #pragma unroll
            for (int mi = 0; mi < 2; mi++)
                #pragma unroll
                for (int j = 0; j < 2; j++) {
                    mma_f16(acc[mi][2 * j + 0], ah[mi], bh[j][0], bh[j][1]);
                    mma_f16(acc[mi][2 * j + 1], ah[mi], bh[j][2], bh[j][3]);
                }
        }
    }

    // Epilogue: bias + tanh-GELU, float2 stores.
    const int row0 = lane >> 2;
    const int cp2  = (lane & 3) * 2;
    #pragma unroll
    for (int mi = 0; mi < 2; mi++) {
        #pragma unroll
        for (int nj = 0; nj < 4; nj++) {
            const int nb = wn + nj * 8 + cp2;
            const float b0 = __ldg(&bias[r * 64 + nb]);
            const float b1 = __ldg(&bias[r * 64 + nb + 1]);
            #pragma unroll
            for (int h = 0; h < 2; h++) {
                const int m = wt + mi * 16 + row0 + h * 8;
                float2 o;
                o.x = gelu_tanh(acc[mi][nj][2 * h + 0] + b0);
                o.y = gelu_tanh(acc[mi][nj][2 * h + 1] + b1);
                *(float2*)&out[(size_t)(t0 + m) * MDIM + r * 64 + nb] = o;
            }
        }
    }
}

// ---------------------------------------------------------------------------
extern "C" void kernel_launch(void* const* d_in, const int* in_sizes, int n_in,
                              void* d_out, int out_size)
{
    const float* x      = (const float*)d_in[0];
    const float* values = (const float*)d_in[1];
    const float* bias   = (const float*)d_in[2];
    const int*   brows  = (const int*)d_in[3];
    const int*   bcols  = (const int*)d_in[4];
    float*       out    = (float*)d_out;

    const int n_blocks = in_sizes[3];
    const int x_elems  = in_sizes[0];
    const int v_elems  = in_sizes[1];

    cudaFuncSetAttribute(fsl_hmma_kernel,
                         cudaFuncAttributeMaxDynamicSharedMemorySize, SMEM_TOTAL);

    prepass_kernel<<<1 + XBLK + VBLK, 256>>>(x, values, brows,
                                             x_elems / 4, v_elems / 4, n_blocks);

    fsl_hmma_kernel<<<1024, 256, SMEM_TOTAL>>>(bias, bcols, out);
}

// round 14
// speedup vs baseline: 1.1554x; 1.1155x over previous
#include <cuda_runtime.h>
#include <cuda_fp16.h>
#include <cstdint>

// Shapes (fixed): x (2048,4096) fp32, values (1024,64,64) fp32, bias (4096,),
// block_rows/cols (1024,) int32 in [0,64), out (2048,4096) fp32.
#define KDIM  4096
#define MDIM  4096
#define TTOK  2048
#define NBMAX 1024
#define MT    128            // tokens per CTA
#define NT    64             // out features per CTA (one row block)

// Half-block staging: K=32 per stage, row pitch 40 fp16 = 80 B (16B multiple,
// 80*r mod 128 distinct for r=0..7 -> ldmatrix conflict-free).
#define PITCHB  80
#define XB      (128 * PITCHB)        // 10240
#define VB      (64  * PITCHB)        // 5120
#define STAGE   (XB + VB)             // 15360
#define NSTG    4
#define SMEM_TOTAL (NSTG * STAGE)     // 61440 -> 3 CTAs/SM

// ---- device scratch (static globals; no allocations allowed) ----
__device__ __half g_xh[TTOK * KDIM];          // 16 MB
__device__ __half g_vh[NBMAX * 64 * 64];      // 8 MB
__device__ int g_row_list[64 * NBMAX];
__device__ int g_row_cnt[64];

// ---- PTX helpers (baseline sm_80+ features only) ----
__device__ __forceinline__ uint32_t smem_u32(const void* p) {
    uint32_t a;
    asm("{ .reg .u64 t; cvta.to.shared.u64 t, %1; cvt.u32.u64 %0, t; }" : "=r"(a) : "l"(p));
    return a;
}
__device__ __forceinline__ void cp_async16(uint32_t saddr, const void* gaddr) {
    asm volatile("cp.async.cg.shared.global [%0], [%1], 16;" :: "r"(saddr), "l"(gaddr));
}
#define CP_COMMIT() asm volatile("cp.async.commit_group;" ::: "memory")
#define CP_WAIT(n)  asm volatile("cp.async.wait_group %0;" :: "n"(n) : "memory")

__device__ __forceinline__ void ldsm_x4(uint32_t* r, uint32_t addr) {
    asm volatile("ldmatrix.sync.aligned.m8n8.x4.shared.b16 {%0,%1,%2,%3}, [%4];"
                 : "=r"(r[0]), "=r"(r[1]), "=r"(r[2]), "=r"(r[3]) : "r"(addr));
}
__device__ __forceinline__ void mma_f16(float* d, const uint32_t* a, uint32_t b0, uint32_t b1) {
    asm volatile(
        "mma.sync.aligned.m16n8k16.row.col.f32.f16.f16.f32 "
        "{%0,%1,%2,%3}, {%4,%5,%6,%7}, {%8,%9}, {%0,%1,%2,%3};"
        : "+f"(d[0]), "+f"(d[1]), "+f"(d[2]), "+f"(d[3])
        : "r"(a[0]), "r"(a[1]), "r"(a[2]), "r"(a[3]), "r"(b0), "r"(b1));
}

__device__ __forceinline__ float gelu_tanh(float v) {
    float inner = 0.7978845608f * (v + 0.044715f * v * v * v);
    return 0.5f * v * (1.0f + tanhf(inner));
}

// ---------------------------------------------------------------------------
// SINGLE fused pre-pass launch, properly parallel:
//   blocks 0..63:        per-row list for row b (warp 0 scans; ~1.5us, hidden)
//   blocks 64..64+XBLK:  x fp32 -> fp16
//   remaining blocks:    values fp32 -> fp16
// ---------------------------------------------------------------------------
#define LBLK 64
#define XBLK 2048
#define VBLK 1024
__global__ void __launch_bounds__(256) prepass_kernel(
    const float* __restrict__ x, const float* __restrict__ values,
    const int* __restrict__ brows,
    int nx4, int nv4, int nb)
{
    const int b = blockIdx.x;
    if (b < LBLK) {
        if (threadIdx.x >= 32) return;       // warp 0 only
        const int r = b, lane = threadIdx.x;
        int cnt = 0;
        for (int base = 0; base < nb; base += 32) {
            int n = base + lane;
            int row = (n < nb) ? brows[n] : -1;
            unsigned m = __ballot_sync(0xFFFFFFFFu, row == r);
            if (row == r)
                g_row_list[r * NBMAX + cnt + __popc(m & ((1u << lane) - 1u))] = n;
            cnt += __popc(m);
        }
        if (lane == 0) g_row_cnt[r] = cnt;
        return;
    }

    const float4* s4;
    uint2* dst;
    int n4, start, stride;
    if (b < LBLK + XBLK) {
        s4 = (const float4*)x; dst = (uint2*)g_xh; n4 = nx4;
        start = (b - LBLK) * 256 + threadIdx.x; stride = XBLK * 256;
    } else {
        s4 = (const float4*)values; dst = (uint2*)g_vh; n4 = nv4;
        start = (b - LBLK - XBLK) * 256 + threadIdx.x; stride = VBLK * 256;
    }
    for (int i = start; i < n4; i += stride) {
        float4 v = s4[i];
        __half2 a = __floats2half2_rn(v.x, v.y);
        __half2 c = __floats2half2_rn(v.z, v.w);
        uint2 o{*(uint32_t*)&a, *(uint32_t*)&c};
        dst[i] = o;
    }
}

// ---------------------------------------------------------------------------
// Half-stage loader: K=32 slice of X and V into stage s. 3 cp.async/thread.
// ---------------------------------------------------------------------------
__device__ __forceinline__ void load_half(uint32_t sb, int s, int n, int c, int kh,
                                          int t0, int tid)
{
    const uint32_t xs = sb + s * STAGE;
    const uint32_t vs = xs + XB;
    const int k0 = c * 64 + kh * 32;
    #pragma unroll
    for (int i = 0; i < 2; i++) {
        const int id = tid + i * 256;
        const int row = id >> 2, cb = id & 3;
        const size_t g = (size_t)(t0 + row) * KDIM + k0 + cb * 8;
        cp_async16(xs + row * PITCHB + cb * 16, g_xh + g);
    }
    {
        const int row = tid >> 2, cb = tid & 3;
        const size_t g = (size_t)n * 4096 + row * 64 + kh * 32 + cb * 8;
        cp_async16(vs + row * PITCHB + cb * 16, g_vh + g);
    }
}

// ---------------------------------------------------------------------------
// Main kernel (hot loop identical to the 99.1us R9 version): 256 threads =
// 8 warps (4 token x 2 n), warp tile 32x32, fp16 HMMA, fp32 accum, 4-stage
// K32 cp.async pipeline. LPT row selection computed in-prologue from
// g_row_cnt (no separate order kernel).
// ---------------------------------------------------------------------------
__global__ void __launch_bounds__(256, 3) fsl_hmma_kernel(
    const float* __restrict__ bias,
    const int*   __restrict__ bcols,
    float*       __restrict__ out)
{
    extern __shared__ char smem[];
    __shared__ int s_cnts[64];
    __shared__ int s_row;
    const uint32_t sb = smem_u32(smem);
    const int tid  = threadIdx.x;
    const int warp = tid >> 5;
    const int lane = tid & 31;
    const int slab = blockIdx.x & 15;
    const int trank = blockIdx.x >> 4;         // target LPT rank
    const int t0   = slab * MT;

    // LPT prologue: thread i<64 computes rank of row i; the match publishes.
    if (tid < 64) s_cnts[tid] = g_row_cnt[tid];
    __syncthreads();
    if (tid < 64) {
        const int c = s_cnts[tid];
        int rank = 0;
        #pragma unroll
        for (int j = 0; j < 64; j++) {
            const int cj = s_cnts[j];
            rank += (cj > c) || (cj == c && j < tid);
        }
        if (rank == trank) s_row = tid;
    }
    __syncthreads();
    const int r = s_row;

    const int wt = (warp >> 1) * 32;
    const int wn = (warp & 1) * 32;

    const int cnt   = s_cnts[r];
    const int total = 2 * cnt;                 // half-block stages
    const int* list = &g_row_list[r * NBMAX];

    float acc[2][4][4];
    #pragma unroll
    for (int mi = 0; mi < 2; mi++)
        #pragma unroll
        for (int nj = 0; nj < 4; nj++)
            #pragma unroll
            for (int q = 0; q < 4; q++) acc[mi][nj][q] = 0.0f;

    // ldmatrix lane-address components (mapping validated R4-R13)
    const int a_m = (lane & 7) + ((lane >> 3) & 1) * 8;
    const int a_k = (lane >> 4) * 8;
    const int b_n = (lane & 7) + ((lane >> 4) & 1) * 8;
    const int b_k = ((lane >> 3) & 1) * 8;

    // Prologue: prime 3 of 4 stages. Stage j = block list[j>>1], half j&1.
    #pragma unroll
    for (int j = 0; j < 3; j++) {
        if (j < total) {
            const int n = list[j >> 1];
            load_half(sb, j, n, __ldg(&bcols[n]), j & 1, t0, tid);
        }
        CP_COMMIT();
    }

    for (int i = 0; i < total; i++) {
        CP_WAIT(2);
        __syncthreads();

        // Refill the stage freed last iteration (overlaps compute)
        if (i + 3 < total) {
            const int j = i + 3;
            const int n = list[j >> 1];
            load_half(sb, (i + 3) & 3, n, __ldg(&bcols[n]), j & 1, t0, tid);
        }
        CP_COMMIT();

        const uint32_t xs = sb + (i & 3) * STAGE;
        const uint32_t vs = xs + XB;

        #pragma unroll
        for (int kc = 0; kc < 2; kc++) {
            uint32_t ah[2][4], bh[2][4];
            const uint32_t ao = (wt + a_m) * PITCHB + (kc * 16 + a_k) * 2;
            const uint32_t bo = (wn + b_n) * PITCHB + (kc * 16 + b_k) * 2;
            #pragma unroll
            for (int mi = 0; mi < 2; mi++)
                ldsm_x4(ah[mi], xs + ao + mi * 16 * PITCHB);
            #pragma unroll
            for (int j = 0; j < 2; j++)
                ldsm_x4(bh[j], vs + bo + j * 16 * PITCHB);
            #pragma unroll
            for (int mi = 0; mi < 2; mi++)
                #pragma unroll
                for (int j = 0; j < 2; j++) {
                    mma_f16(acc[mi][2 * j + 0], ah[mi], bh[j][0], bh[j][1]);
                    mma_f16(acc[mi][2 * j + 1], ah[mi], bh[j][2], bh[j][3]);
                }
        }
    }

    // Epilogue: bias + tanh-GELU, float2 stores.
    const int row0 = lane >> 2;
    const int cp2  = (lane & 3) * 2;
    #pragma unroll
    for (int mi = 0; mi < 2; mi++) {
        #pragma unroll
        for (int nj = 0; nj < 4; nj++) {
            const int nb = wn + nj * 8 + cp2;
            const float b0 = __ldg(&bias[r * 64 + nb]);
            const float b1 = __ldg(&bias[r * 64 + nb + 1]);
            #pragma unroll
            for (int h = 0; h < 2; h++) {
                const int m = wt + mi * 16 + row0 + h * 8;
                float2 o;
                o.x = gelu_tanh(acc[mi][nj][2 * h + 0] + b0);
                o.y = gelu_tanh(acc[mi][nj][2 * h + 1] + b1);
                *(float2*)&out[(size_t)(t0 + m) * MDIM + r * 64 + nb] = o;
            }
        }
    }
}

// ---------------------------------------------------------------------------
extern "C" void kernel_launch(void* const* d_in, const int* in_sizes, int n_in,
                              void* d_out, int out_size)
{
    const float* x      = (const float*)d_in[0];
    const float* values = (const float*)d_in[1];
    const float* bias   = (const float*)d_in[2];
    const int*   brows  = (const int*)d_in[3];
    const int*   bcols  = (const int*)d_in[4];
    float*       out    = (float*)d_out;

    const int n_blocks = in_sizes[3];
    const int x_elems  = in_sizes[0];
    const int v_elems  = in_sizes[1];

    cudaFuncSetAttribute(fsl_hmma_kernel,
                         cudaFuncAttributeMaxDynamicSharedMemorySize, SMEM_TOTAL);

    prepass_kernel<<<LBLK + XBLK + VBLK, 256>>>(x, values, brows,
                                                x_elems / 4, v_elems / 4, n_blocks);

    fsl_hmma_kernel<<<1024, 256, SMEM_TOTAL>>>(bias, bcols, out);
}

// round 15
// speedup vs baseline: 1.2346x; 1.0686x over previous
#include <cuda_runtime.h>
#include <cuda_fp16.h>
#include <cstdint>

// Shapes (fixed): x (2048,4096) fp32, values (1024,64,64) fp32, bias (4096,),
// block_rows/cols (1024,) int32 in [0,64), out (2048,4096) fp32.
#define KDIM  4096
#define MDIM  4096
#define TTOK  2048
#define NBMAX 1024
#define MT    128            // tokens per CTA
#define NT    64             // out features per CTA (one row block)

// Half-block staging: K=32 per stage, row pitch 40 fp16 = 80 B (16B multiple,
// 80*r mod 128 distinct for r=0..7 -> ldmatrix conflict-free).
#define PITCHB  80
#define XB      (128 * PITCHB)        // 10240
#define VB      (64  * PITCHB)        // 5120
#define STAGE   (XB + VB)             // 15360
#define NSTG    3
#define SMEM_TOTAL (NSTG * STAGE)     // 46080 -> 4 CTAs/SM

// ---- device scratch (static globals; no allocations allowed) ----
__device__ __half g_xh[TTOK * KDIM];          // 16 MB
__device__ __half g_vh[NBMAX * 64 * 64];      // 8 MB
__device__ int g_row_list[64 * NBMAX];
__device__ int g_row_cnt[64];

// ---- PTX helpers (baseline sm_80+ features only) ----
__device__ __forceinline__ uint32_t smem_u32(const void* p) {
    uint32_t a;
    asm("{ .reg .u64 t; cvta.to.shared.u64 t, %1; cvt.u32.u64 %0, t; }" : "=r"(a) : "l"(p));
    return a;
}
__device__ __forceinline__ void cp_async16(uint32_t saddr, const void* gaddr) {
    asm volatile("cp.async.cg.shared.global [%0], [%1], 16;" :: "r"(saddr), "l"(gaddr));
}
#define CP_COMMIT() asm volatile("cp.async.commit_group;" ::: "memory")
#define CP_WAIT(n)  asm volatile("cp.async.wait_group %0;" :: "n"(n) : "memory")

__device__ __forceinline__ void ldsm_x4(uint32_t* r, uint32_t addr) {
    asm volatile("ldmatrix.sync.aligned.m8n8.x4.shared.b16 {%0,%1,%2,%3}, [%4];"
                 : "=r"(r[0]), "=r"(r[1]), "=r"(r[2]), "=r"(r[3]) : "r"(addr));
}
__device__ __forceinline__ void mma_f16(float* d, const uint32_t* a, uint32_t b0, uint32_t b1) {
    asm volatile(
        "mma.sync.aligned.m16n8k16.row.col.f32.f16.f16.f32 "
        "{%0,%1,%2,%3}, {%4,%5,%6,%7}, {%8,%9}, {%0,%1,%2,%3};"
        : "+f"(d[0]), "+f"(d[1]), "+f"(d[2]), "+f"(d[3])
        : "r"(a[0]), "r"(a[1]), "r"(a[2]), "r"(a[3]), "r"(b0), "r"(b1));
}

__device__ __forceinline__ float gelu_tanh(float v) {
    float inner = 0.7978845608f * (v + 0.044715f * v * v * v);
    return 0.5f * v * (1.0f + tanhf(inner));
}

// ---------------------------------------------------------------------------
// SINGLE fused pre-pass launch, properly parallel:
//   blocks 0..63:        per-row list for row b (warp 0 scans; hidden)
//   blocks 64..64+XBLK:  x fp32 -> fp16
//   remaining blocks:    values fp32 -> fp16
// ---------------------------------------------------------------------------
#define LBLK 64
#define XBLK 2048
#define VBLK 1024
__global__ void __launch_bounds__(256) prepass_kernel(
    const float* __restrict__ x, const float* __restrict__ values,
    const int* __restrict__ brows,
    int nx4, int nv4, int nb)
{
    const int b = blockIdx.x;
    if (b < LBLK) {
        if (threadIdx.x >= 32) return;       // warp 0 only
        const int r = b, lane = threadIdx.x;
        int cnt = 0;
        for (int base = 0; base < nb; base += 32) {
            int n = base + lane;
            int row = (n < nb) ? brows[n] : -1;
            unsigned m = __ballot_sync(0xFFFFFFFFu, row == r);
            if (row == r)
                g_row_list[r * NBMAX + cnt + __popc(m & ((1u << lane) - 1u))] = n;
            cnt += __popc(m);
        }
        if (lane == 0) g_row_cnt[r] = cnt;
        return;
    }

    const float4* s4;
    uint2* dst;
    int n4, start, stride;
    if (b < LBLK + XBLK) {
        s4 = (const float4*)x; dst = (uint2*)g_xh; n4 = nx4;
        start = (b - LBLK) * 256 + threadIdx.x; stride = XBLK * 256;
    } else {
        s4 = (const float4*)values; dst = (uint2*)g_vh; n4 = nv4;
        start = (b - LBLK - XBLK) * 256 + threadIdx.x; stride = VBLK * 256;
    }
    for (int i = start; i < n4; i += stride) {
        float4 v = s4[i];
        __half2 a = __floats2half2_rn(v.x, v.y);
        __half2 c = __floats2half2_rn(v.z, v.w);
        uint2 o{*(uint32_t*)&a, *(uint32_t*)&c};
        dst[i] = o;
    }
}

// ---------------------------------------------------------------------------
// Half-stage loader: K=32 slice of X and V into stage s. 3 cp.async/thread.
// ---------------------------------------------------------------------------
__device__ __forceinline__ void load_half(uint32_t sb, int s, int n, int c, int kh,
                                          int t0, int tid)
{
    const uint32_t xs = sb + s * STAGE;
    const uint32_t vs = xs + XB;
    const int k0 = c * 64 + kh * 32;
    #pragma unroll
    for (int i = 0; i < 2; i++) {
        const int id = tid + i * 256;
        const int row = id >> 2, cb = id & 3;
        const size_t g = (size_t)(t0 + row) * KDIM + k0 + cb * 8;
        cp_async16(xs + row * PITCHB + cb * 16, g_xh + g);
    }
    {
        const int row = tid >> 2, cb = tid & 3;
        const size_t g = (size_t)n * 4096 + row * 64 + kh * 32 + cb * 8;
        cp_async16(vs + row * PITCHB + cb * 16, g_vh + g);
    }
}

// ---------------------------------------------------------------------------
// Main kernel: hot loop identical math to R9/R14; NSTG=3 + launch_bounds
// (256,4) -> 4 CTAs/SM (32 warps) for latency hiding. Pipeline: prime 2,
// CP_WAIT(1), prefetch i+2 (stage reuse fenced by the per-iter barrier).
// ---------------------------------------------------------------------------
__global__ void __launch_bounds__(256, 4) fsl_hmma_kernel(
    const float* __restrict__ bias,
    const int*   __restrict__ bcols,
    float*       __restrict__ out)
{
    extern __shared__ char smem[];
    __shared__ int s_cnts[64];
    __shared__ int s_row;
    const uint32_t sb = smem_u32(smem);
    const int tid  = threadIdx.x;
    const int warp = tid >> 5;
    const int lane = tid & 31;
    const int slab = blockIdx.x & 15;
    const int trank = blockIdx.x >> 4;         // target LPT rank
    const int t0   = slab * MT;

    // LPT prologue: thread i<64 computes rank of row i; the match publishes.
    if (tid < 64) s_cnts[tid] = g_row_cnt[tid];
    __syncthreads();
    if (tid < 64) {
        const int c = s_cnts[tid];
        int rank = 0;
        #pragma unroll
        for (int j = 0; j < 64; j++) {
            const int cj = s_cnts[j];
            rank += (cj > c) || (cj == c && j < tid);
        }
        if (rank == trank) s_row = tid;
    }
    __syncthreads();
    const int r = s_row;

    const int wt = (warp >> 1) * 32;
    const int wn = (warp & 1) * 32;

    const int cnt   = s_cnts[r];
    const int total = 2 * cnt;                 // half-block stages
    const int* list = &g_row_list[r * NBMAX];

    float acc[2][4][4];
    #pragma unroll
    for (int mi = 0; mi < 2; mi++)
        #pragma unroll
        for (int nj = 0; nj < 4; nj++)
            #pragma unroll
            for (int q = 0; q < 4; q++) acc[mi][nj][q] = 0.0f;

    // ldmatrix lane-address components (mapping validated R4-R14)
    const int a_m = (lane & 7) + ((lane >> 3) & 1) * 8;
    const int a_k = (lane >> 4) * 8;
    const int b_n = (lane & 7) + ((lane >> 4) & 1) * 8;
    const int b_k = ((lane >> 3) & 1) * 8;

    // Prologue: prime 2 of 3 stages. Stage j = block list[j>>1], half j&1.
    #pragma unroll
    for (int j = 0; j < 2; j++) {
        if (j < total) {
            const int n = list[j >> 1];
            load_half(sb, j, n, __ldg(&bcols[n]), j & 1, t0, tid);
        }
        CP_COMMIT();
    }

    int s = 0;                                  // stage of iteration i (mod 3)
    for (int i = 0; i < total; i++) {
        CP_WAIT(1);
        __syncthreads();

        // Refill the stage freed last iteration (overlaps compute)
        if (i + 2 < total) {
            const int j = i + 2;
            const int n = list[j >> 1];
            int ps = s + 2; if (ps >= NSTG) ps -= NSTG;
            load_half(sb, ps, n, __ldg(&bcols[n]), j & 1, t0, tid);
        }
        CP_COMMIT();

        const uint32_t xs = sb + s * STAGE;
        const uint32_t vs = xs + XB;
        if (++s == NSTG) s = 0;

        #pragma unroll
        for (int kc = 0; kc < 2; kc++) {
            uint32_t ah[2][4], bh[2][4];
            const uint32_t ao = (wt + a_m) * PITCHB + (kc * 16 + a_k) * 2;
            const uint32_t bo = (wn + b_n) * PITCHB + (kc * 16 + b_k) * 2;
            #pragma unroll
            for (int mi = 0; mi < 2; mi++)
                ldsm_x4(ah[mi], xs + ao + mi * 16 * PITCHB);
            #pragma unroll
            for (int j = 0; j < 2; j++)
                ldsm_x4(bh[j], vs + bo + j * 16 * PITCHB);
            #pragma unroll
            for (int mi = 0; mi < 2; mi++)
                #pragma unroll
                for (int j = 0; j < 2; j++) {
                    mma_f16(acc[mi][2 * j + 0], ah[mi], bh[j][0], bh[j][1]);
                    mma_f16(acc[mi][2 * j + 1], ah[mi], bh[j][2], bh[j][3]);
                }
        }
    }

    // Epilogue: bias + tanh-GELU, float2 stores.
    const int row0 = lane >> 2;
    const int cp2  = (lane & 3) * 2;
    #pragma unroll
    for (int mi = 0; mi < 2; mi++) {
        #pragma unroll
        for (int nj = 0; nj < 4; nj++) {
            const int nb = wn + nj * 8 + cp2;
            const float b0 = __ldg(&bias[r * 64 + nb]);
            const float b1 = __ldg(&bias[r * 64 + nb + 1]);
            #pragma unroll
            for (int h = 0; h < 2; h++) {
                const int m = wt + mi * 16 + row0 + h * 8;
                float2 o;
                o.x = gelu_tanh(acc[mi][nj][2 * h + 0] + b0);
                o.y = gelu_tanh(acc[mi][nj][2 * h + 1] + b1);
                *(float2*)&out[(size_t)(t0 + m) * MDIM + r * 64 + nb] = o;
            }
        }
    }
}

// ---------------------------------------------------------------------------
extern "C" void kernel_launch(void* const* d_in, const int* in_sizes, int n_in,
                              void* d_out, int out_size)
{
    const float* x      = (const float*)d_in[0];
    const float* values = (const float*)d_in[1];
    const float* bias   = (const float*)d_in[2];
    const int*   brows  = (const int*)d_in[3];
    const int*   bcols  = (const int*)d_in[4];
    float*       out    = (float*)d_out;

    const int n_blocks = in_sizes[3];
    const int x_elems  = in_sizes[0];
    const int v_elems  = in_sizes[1];

    cudaFuncSetAttribute(fsl_hmma_kernel,
                         cudaFuncAttributeMaxDynamicSharedMemorySize, SMEM_TOTAL);

    prepass_kernel<<<LBLK + XBLK + VBLK, 256>>>(x, values, brows,
                                                x_elems / 4, v_elems / 4, n_blocks);

    fsl_hmma_kernel<<<1024, 256, SMEM_TOTAL>>>(bias, bcols, out);
}

// round 16
// speedup vs baseline: 1.2656x; 1.0251x over previous
#include <cuda_runtime.h>
#include <cuda_fp16.h>
#include <cstdint>

// Shapes (fixed): x (2048,4096) fp32, values (1024,64,64) fp32, bias (4096,),
// block_rows/cols (1024,) int32 in [0,64), out (2048,4096) fp32.
#define KDIM  4096
#define MDIM  4096
#define TTOK  2048
#define NBMAX 1024
#define MT    128            // tokens per CTA
#define NT    64             // out features per CTA (one row block)

// Half-block staging: K=32 per stage, row pitch 40 fp16 = 80 B (16B multiple,
// 80*r mod 128 distinct for r=0..7 -> ldmatrix conflict-free).
#define PITCHB  80
#define XB      (128 * PITCHB)        // 10240
#define VB      (64  * PITCHB)        // 5120
#define STAGE   (XB + VB)             // 15360
#define NSTG    3
#define SMEM_TOTAL (NSTG * STAGE)     // 46080 -> 4 CTAs/SM

// ---- device scratch (static globals; no allocations allowed) ----
__device__ __half g_xh[TTOK * KDIM];          // 16 MB
__device__ __half g_vh[NBMAX * 64 * 64];      // 8 MB
__device__ int g_row_list[64 * NBMAX];
__device__ int g_row_cnt[64];

// ---- PTX helpers (baseline sm_80+ features only) ----
__device__ __forceinline__ uint32_t smem_u32(const void* p) {
    uint32_t a;
    asm("{ .reg .u64 t; cvta.to.shared.u64 t, %1; cvt.u32.u64 %0, t; }" : "=r"(a) : "l"(p));
    return a;
}
__device__ __forceinline__ void cp_async16(uint32_t saddr, const void* gaddr) {
    asm volatile("cp.async.cg.shared.global [%0], [%1], 16;" :: "r"(saddr), "l"(gaddr));
}
#define CP_COMMIT() asm volatile("cp.async.commit_group;" ::: "memory")
#define CP_WAIT(n)  asm volatile("cp.async.wait_group %0;" :: "n"(n) : "memory")

__device__ __forceinline__ void ldsm_x4(uint32_t* r, uint32_t addr) {
    asm volatile("ldmatrix.sync.aligned.m8n8.x4.shared.b16 {%0,%1,%2,%3}, [%4];"
                 : "=r"(r[0]), "=r"(r[1]), "=r"(r[2]), "=r"(r[3]) : "r"(addr));
}
__device__ __forceinline__ void mma_f16(float* d, const uint32_t* a, uint32_t b0, uint32_t b1) {
    asm volatile(
        "mma.sync.aligned.m16n8k16.row.col.f32.f16.f16.f32 "
        "{%0,%1,%2,%3}, {%4,%5,%6,%7}, {%8,%9}, {%0,%1,%2,%3};"
        : "+f"(d[0]), "+f"(d[1]), "+f"(d[2]), "+f"(d[3])
        : "r"(a[0]), "r"(a[1]), "r"(a[2]), "r"(a[3]), "r"(b0), "r"(b1));
}

__device__ __forceinline__ float gelu_tanh(float v) {
    float inner = 0.7978845608f * (v + 0.044715f * v * v * v);
    return 0.5f * v * (1.0f + tanhf(inner));
}

// ---------------------------------------------------------------------------
// SINGLE fused pre-pass launch, properly parallel:
//   blocks 0..63:        per-row list for row b (warp 0 scans; hidden)
//   blocks 64..64+XBLK:  x fp32 -> fp16
//   remaining blocks:    values fp32 -> fp16
// ---------------------------------------------------------------------------
#define LBLK 64
#define XBLK 2048
#define VBLK 1024
__global__ void __launch_bounds__(256) prepass_kernel(
    const float* __restrict__ x, const float* __restrict__ values,
    const int* __restrict__ brows,
    int nx4, int nv4, int nb)
{
    const int b = blockIdx.x;
    if (b < LBLK) {
        if (threadIdx.x >= 32) return;       // warp 0 only
        const int r = b, lane = threadIdx.x;
        int cnt = 0;
        for (int base = 0; base < nb; base += 32) {
            int n = base + lane;
            int row = (n < nb) ? brows[n] : -1;
            unsigned m = __ballot_sync(0xFFFFFFFFu, row == r);
            if (row == r)
                g_row_list[r * NBMAX + cnt + __popc(m & ((1u << lane) - 1u))] = n;
            cnt += __popc(m);
        }
        if (lane == 0) g_row_cnt[r] = cnt;
        return;
    }

    const float4* s4;
    uint2* dst;
    int n4, start, stride;
    if (b < LBLK + XBLK) {
        s4 = (const float4*)x; dst = (uint2*)g_xh; n4 = nx4;
        start = (b - LBLK) * 256 + threadIdx.x; stride = XBLK * 256;
    } else {
        s4 = (const float4*)values; dst = (uint2*)g_vh; n4 = nv4;
        start = (b - LBLK - XBLK) * 256 + threadIdx.x; stride = VBLK * 256;
    }
    for (int i = start; i < n4; i += stride) {
        float4 v = s4[i];
        __half2 a = __floats2half2_rn(v.x, v.y);
        __half2 c = __floats2half2_rn(v.z, v.w);
        uint2 o{*(uint32_t*)&a, *(uint32_t*)&c};
        dst[i] = o;
    }
}

// ---------------------------------------------------------------------------
// Main kernel: hot loop math identical to R15 (86.3us). Address components
// hoisted: per-thread global/smem loader offsets and per-thread ldsm in-stage
// offsets computed once; per iteration only adds remain.
// ---------------------------------------------------------------------------
__global__ void __launch_bounds__(256, 4) fsl_hmma_kernel(
    const float* __restrict__ bias,
    const int*   __restrict__ bcols,
    float*       __restrict__ out)
{
    extern __shared__ char smem[];
    __shared__ int s_cnts[64];
    __shared__ int s_row;
    const uint32_t sb = smem_u32(smem);
    const int tid  = threadIdx.x;
    const int warp = tid >> 5;
    const int lane = tid & 31;
    const int slab = blockIdx.x & 15;
    const int trank = blockIdx.x >> 4;         // target LPT rank
    const int t0   = slab * MT;

    // LPT prologue: thread i<64 computes rank of row i; the match publishes.
    if (tid < 64) s_cnts[tid] = g_row_cnt[tid];
    __syncthreads();
    if (tid < 64) {
        const int c = s_cnts[tid];
        int rank = 0;
        #pragma unroll
        for (int j = 0; j < 64; j++) {
            const int cj = s_cnts[j];
            rank += (cj > c) || (cj == c && j < tid);
        }
        if (rank == trank) s_row = tid;
    }
    __syncthreads();
    const int r = s_row;

    const int wt = (warp >> 1) * 32;
    const int wn = (warp & 1) * 32;

    const int cnt   = s_cnts[r];
    const int total = 2 * cnt;                 // half-block stages
    const int* list = &g_row_list[r * NBMAX];

    // ---- hoisted loader constants (per thread) ----
    const int lx_row = tid >> 2, lx_cb = tid & 3;               // X loader
    const __half* xg0 = g_xh + (t0 + lx_row) * KDIM + lx_cb * 8;
    const __half* xg1 = g_xh + (t0 + lx_row + 64) * KDIM + lx_cb * 8;
    const uint32_t xs_off0 = lx_row * PITCHB + lx_cb * 16;
    const uint32_t xs_off1 = (lx_row + 64) * PITCHB + lx_cb * 16;
    const __half* vg0 = g_vh + lx_row * 64 + lx_cb * 8;         // V loader (+n*4096+kh*32)
    const uint32_t vs_off = XB + lx_row * PITCHB + lx_cb * 16;

    // ---- hoisted ldsm in-stage offsets (per thread) ----
    const int a_m = (lane & 7) + ((lane >> 3) & 1) * 8;
    const int a_k = (lane >> 4) * 8;
    const int b_n = (lane & 7) + ((lane >> 4) & 1) * 8;
    const int b_k = ((lane >> 3) & 1) * 8;
    uint32_t aoff[2][2], boff[2][2];           // [kc][mi] / [kc][j]
    #pragma unroll
    for (int kc = 0; kc < 2; kc++) {
        #pragma unroll
        for (int mi = 0; mi < 2; mi++)
            aoff[kc][mi] = (wt + a_m + mi * 16) * PITCHB + (kc * 16 + a_k) * 2;
        #pragma unroll
        for (int j = 0; j < 2; j++)
            boff[kc][j] = XB + (wn + b_n + j * 16) * PITCHB + (kc * 16 + b_k) * 2;
    }

    float acc[2][4][4];
    #pragma unroll
    for (int mi = 0; mi < 2; mi++)
        #pragma unroll
        for (int nj = 0; nj < 4; nj++)
            #pragma unroll
            for (int q = 0; q < 4; q++) acc[mi][nj][q] = 0.0f;

    // Loader lambda replacement (macro keeps everything in registers)
#define LOAD_HALF(stage_base, n_, c_, kh_) do {                                  \
        const int koff = (c_) * 64 + (kh_) * 32;                                 \
        cp_async16((stage_base) + xs_off0, xg0 + koff);                          \
        cp_async16((stage_base) + xs_off1, xg1 + koff);                         \
        cp_async16((stage_base) + vs_off, vg0 + (n_) * 4096 + (kh_) * 32);       \
    } while (0)

    // Prologue: prime 2 of 3 stages. Stage j = block list[j>>1], half j&1.
    int nxt_n = (total > 0) ? list[0] : 0;
    int nxt_c = (total > 0) ? __ldg(&bcols[nxt_n]) : 0;
    #pragma unroll
    for (int j = 0; j < 2; j++) {
        if (j < total) LOAD_HALF(sb + j * STAGE, nxt_n, nxt_c, j & 1);
        CP_COMMIT();
        if (j == 0 && total > 2) {             // metadata for block 1
            // note: stage 1 is half 1 of block 0; block 1 starts at j=2
        }
    }
    // metadata for the first prefetched stage (j = 2 -> block list[1])
    int pf_n = (total > 2) ? list[1] : 0;
    int pf_c = (total > 2) ? __ldg(&bcols[pf_n]) : 0;

    int s = 0;                                  // stage of iteration i (mod 3)
    for (int i = 0; i < total; i++) {
        CP_WAIT(1);
        __syncthreads();

        // Refill the stage freed last iteration (overlaps compute)
        const int j = i + 2;
        if (j < total) {
            int ps = s + 2; if (ps >= NSTG) ps -= NSTG;
            LOAD_HALF(sb + ps * STAGE, pf_n, pf_c, j & 1);
            // prefetch metadata for the NEXT stage (j+1) well ahead of use
            const int jn = j + 1;
            if (jn < total && (jn & 1) == 0) {
                pf_n = list[jn >> 1];
                pf_c = __ldg(&bcols[pf_n]);
            }
        }
        CP_COMMIT();

        const uint32_t xs = sb + s * STAGE;
        if (++s == NSTG) s = 0;

        #pragma unroll
        for (int kc = 0; kc < 2; kc++) {
            uint32_t ah[2][4], bh[2][4];
            #pragma unroll
            for (int mi = 0; mi < 2; mi++)
                ldsm_x4(ah[mi], xs + aoff[kc][mi]);
            #pragma unroll
            for (int j2 = 0; j2 < 2; j2++)
                ldsm_x4(bh[j2], xs + boff[kc][j2]);
            #pragma unroll
            for (int mi = 0; mi < 2; mi++)
                #pragma unroll
                for (int j2 = 0; j2 < 2; j2++) {
                    mma_f16(acc[mi][2 * j2 + 0], ah[mi], bh[j2][0], bh[j2][1]);
                    mma_f16(acc[mi][2 * j2 + 1], ah[mi], bh[j2][2], bh[j2][3]);
                }
        }
    }

    // Epilogue: bias + tanh-GELU, float2 stores.
    const int row0 = lane >> 2;
    const int cp2  = (lane & 3) * 2;
    #pragma unroll
    for (int mi = 0; mi < 2; mi++) {
        #pragma unroll
        for (int nj = 0; nj < 4; nj++) {
            const int nb = wn + nj * 8 + cp2;
            const float b0 = __ldg(&bias[r * 64 + nb]);
            const float b1 = __ldg(&bias[r * 64 + nb + 1]);
            #pragma unroll
            for (int h = 0; h < 2; h++) {
                const int m = wt + mi * 16 + row0 + h * 8;
                float2 o;
                o.x = gelu_tanh(acc[mi][nj][2 * h + 0] + b0);
                o.y = gelu_tanh(acc[mi][nj][2 * h + 1] + b1);
                *(float2*)&out[(size_t)(t0 + m) * MDIM + r * 64 + nb] = o;
            }
        }
    }
#undef LOAD_HALF
}

// ---------------------------------------------------------------------------
extern "C" void kernel_launch(void* const* d_in, const int* in_sizes, int n_in,
                              void* d_out, int out_size)
{
    const float* x      = (const float*)d_in[0];
    const float* values = (const float*)d_in[1];
    const float* bias   = (const float*)d_in[2];
    const int*   brows  = (const int*)d_in[3];
    const int*   bcols  = (const int*)d_in[4];
    float*       out    = (float*)d_out;

    const int n_blocks = in_sizes[3];
    const int x_elems  = in_sizes[0];
    const int v_elems  = in_sizes[1];

    cudaFuncSetAttribute(fsl_hmma_kernel,
                         cudaFuncAttributeMaxDynamicSharedMemorySize, SMEM_TOTAL);

    prepass_kernel<<<LBLK + XBLK + VBLK, 256>>>(x, values, brows,
                                                x_elems / 4, v_elems / 4, n_blocks);

    fsl_hmma_kernel<<<1024, 256, SMEM_TOTAL>>>(bias, bcols, out);
}

// round 17
// speedup vs baseline: 1.4013x; 1.1073x over previous
#include <cuda_runtime.h>
#include <cuda_fp16.h>
#include <cstdint>

// Shapes (fixed): x (2048,4096) fp32, values (1024,64,64) fp32, bias (4096,),
// block_rows/cols (1024,) int32 in [0,64), out (2048,4096) fp32.
#define KDIM  4096
#define MDIM  4096
#define TTOK  2048
#define NBMAX 1024
#define MT    128            // tokens per CTA
#define NT    64             // out features per CTA (one row block)

// FULL-block staging: K=64 per stage, row pitch 144 B (16B multiple, and
// 16*r mod 128 distinct for r=0..7 -> ldmatrix conflict-free).
#define PITCHB  144
#define XB      (128 * PITCHB)        // 18432
#define VB      (64  * PITCHB)        // 9216
#define STAGE   (XB + VB)             // 27648
#define NSTG    2
#define SMEM_TOTAL (NSTG * STAGE)     // 55296 <= 57344 -> 4 CTAs/SM

// ---- device scratch (static globals; no allocations allowed) ----
__device__ __half g_xh[TTOK * KDIM];          // 16 MB
__device__ __half g_vh[NBMAX * 64 * 64];      // 8 MB
__device__ int g_row_list[64 * NBMAX];
__device__ int g_row_cnt[64];

// ---- PTX helpers (baseline sm_80+ features only) ----
__device__ __forceinline__ uint32_t smem_u32(const void* p) {
    uint32_t a;
    asm("{ .reg .u64 t; cvta.to.shared.u64 t, %1; cvt.u32.u64 %0, t; }" : "=r"(a) : "l"(p));
    return a;
}
__device__ __forceinline__ void cp_async16(uint32_t saddr, const void* gaddr) {
    asm volatile("cp.async.cg.shared.global [%0], [%1], 16;" :: "r"(saddr), "l"(gaddr));
}
#define CP_COMMIT() asm volatile("cp.async.commit_group;" ::: "memory")
#define CP_WAIT(n)  asm volatile("cp.async.wait_group %0;" :: "n"(n) : "memory")

__device__ __forceinline__ void ldsm_x4(uint32_t* r, uint32_t addr) {
    asm volatile("ldmatrix.sync.aligned.m8n8.x4.shared.b16 {%0,%1,%2,%3}, [%4];"
                 : "=r"(r[0]), "=r"(r[1]), "=r"(r[2]), "=r"(r[3]) : "r"(addr));
}
__device__ __forceinline__ void mma_f16(float* d, const uint32_t* a, uint32_t b0, uint32_t b1) {
    asm volatile(
        "mma.sync.aligned.m16n8k16.row.col.f32.f16.f16.f32 "
        "{%0,%1,%2,%3}, {%4,%5,%6,%7}, {%8,%9}, {%0,%1,%2,%3};"
        : "+f"(d[0]), "+f"(d[1]), "+f"(d[2]), "+f"(d[3])
        : "r"(a[0]), "r"(a[1]), "r"(a[2]), "r"(a[3]), "r"(b0), "r"(b1));
}

__device__ __forceinline__ float gelu_tanh(float v) {
    float inner = 0.7978845608f * (v + 0.044715f * v * v * v);
    return 0.5f * v * (1.0f + tanhf(inner));
}

// ---------------------------------------------------------------------------
// SINGLE fused pre-pass launch (unchanged from the 84.2us config):
//   blocks 0..63:        per-row list for row b (warp 0 scans; hidden)
//   blocks 64..64+XBLK:  x fp32 -> fp16
//   remaining blocks:    values fp32 -> fp16
// ---------------------------------------------------------------------------
#define LBLK 64
#define XBLK 2048
#define VBLK 1024
__global__ void __launch_bounds__(256) prepass_kernel(
    const float* __restrict__ x, const float* __restrict__ values,
    const int* __restrict__ brows,
    int nx4, int nv4, int nb)
{
    const int b = blockIdx.x;
    if (b < LBLK) {
        if (threadIdx.x >= 32) return;       // warp 0 only
        const int r = b, lane = threadIdx.x;
        int cnt = 0;
        for (int base = 0; base < nb; base += 32) {
            int n = base + lane;
            int row = (n < nb) ? brows[n] : -1;
            unsigned m = __ballot_sync(0xFFFFFFFFu, row == r);
            if (row == r)
                g_row_list[r * NBMAX + cnt + __popc(m & ((1u << lane) - 1u))] = n;
            cnt += __popc(m);
        }
        if (lane == 0) g_row_cnt[r] = cnt;
        return;
    }

    const float4* s4;
    uint2* dst;
    int n4, start, stride;
    if (b < LBLK + XBLK) {
        s4 = (const float4*)x; dst = (uint2*)g_xh; n4 = nx4;
        start = (b - LBLK) * 256 + threadIdx.x; stride = XBLK * 256;
    } else {
        s4 = (const float4*)values; dst = (uint2*)g_vh; n4 = nv4;
        start = (b - LBLK - XBLK) * 256 + threadIdx.x; stride = VBLK * 256;
    }
    for (int i = start; i < n4; i += stride) {
        float4 v = s4[i];
        __half2 a = __floats2half2_rn(v.x, v.y);
        __half2 c = __floats2half2_rn(v.z, v.w);
        uint2 o{*(uint32_t*)&a, *(uint32_t*)&c};
        dst[i] = o;
    }
}

// ---------------------------------------------------------------------------
// Main kernel: K=64 double-buffered stages (one barrier per BLOCK, half the
// R16 barrier rate), 4 CTAs/SM. 8 warps (4 token x 2 n), warp tile 32x32,
// fp16 HMMA, fp32 accum. Per-accumulator k-order identical to R9..R16.
// ---------------------------------------------------------------------------
__global__ void __launch_bounds__(256, 4) fsl_hmma_kernel(
    const float* __restrict__ bias,
    const int*   __restrict__ bcols,
    float*       __restrict__ out)
{
    extern __shared__ char smem[];
    __shared__ int s_cnts[64];
    __shared__ int s_row;
    const uint32_t sb = smem_u32(smem);
    const int tid  = threadIdx.x;
    const int warp = tid >> 5;
    const int lane = tid & 31;
    const int slab = blockIdx.x & 15;
    const int trank = blockIdx.x >> 4;         // target LPT rank
    const int t0   = slab * MT;

    // LPT prologue: thread i<64 computes rank of row i; the match publishes.
    if (tid < 64) s_cnts[tid] = g_row_cnt[tid];
    __syncthreads();
    if (tid < 64) {
        const int c = s_cnts[tid];
        int rank = 0;
        #pragma unroll
        for (int j = 0; j < 64; j++) {
            const int cj = s_cnts[j];
            rank += (cj > c) || (cj == c && j < tid);
        }
        if (rank == trank) s_row = tid;
    }
    __syncthreads();
    const int r = s_row;

    const int wt = (warp >> 1) * 32;
    const int wn = (warp & 1) * 32;

    const int cnt   = s_cnts[r];
    const int* list = &g_row_list[r * NBMAX];

    // ---- hoisted loader constants (per thread): 8 chunks/row of 16B ----
    const int lx_row = tid >> 3, lx_cb = tid & 7;
    // X: 128 rows x 8 chunks = 1024 chunks, 4 per thread (rows +32 apart)
    const __half* xg0 = g_xh + (t0 + lx_row) * KDIM + lx_cb * 8;
    const uint32_t xs_off = lx_row * PITCHB + lx_cb * 16;
    // V: 64 rows x 8 chunks = 512 chunks, 2 per thread (rows +32 apart)
    const __half* vg0 = g_vh + lx_row * 64 + lx_cb * 8;      // + n*4096
    const uint32_t vs_off = XB + lx_row * PITCHB + lx_cb * 16;

    // ---- hoisted ldsm in-stage base offsets (per thread); +kc*32 per step ----
    const int a_m = (lane & 7) + ((lane >> 3) & 1) * 8;
    const int a_k = (lane >> 4) * 8;
    const int b_n = (lane & 7) + ((lane >> 4) & 1) * 8;
    const int b_k = ((lane >> 3) & 1) * 8;
    uint32_t aoff[2], boff[2];
    #pragma unroll
    for (int mi = 0; mi < 2; mi++)
        aoff[mi] = (wt + a_m + mi * 16) * PITCHB + a_k * 2;
    #pragma unroll
    for (int j = 0; j < 2; j++)
        boff[j] = XB + (wn + b_n + j * 16) * PITCHB + b_k * 2;

    float acc[2][4][4];
    #pragma unroll
    for (int mi = 0; mi < 2; mi++)
        #pragma unroll
        for (int nj = 0; nj < 4; nj++)
            #pragma unroll
            for (int q = 0; q < 4; q++) acc[mi][nj][q] = 0.0f;

#define LOAD_BLOCK(stage_base, n_, c_) do {                                      \
        const int koff = (c_) * 64;                                              \
        _Pragma("unroll")                                                        \
        for (int ii = 0; ii < 4; ii++)                                           \
            cp_async16((stage_base) + xs_off + ii * (32 * PITCHB),               \
                       xg0 + koff + ii * (32 * KDIM));                           \
        _Pragma("unroll")                                                        \
        for (int ii = 0; ii < 2; ii++)                                           \
            cp_async16((stage_base) + vs_off + ii * (32 * PITCHB),               \
                       vg0 + (n_) * 4096 + ii * (32 * 64));                      \
    } while (0)

    // Prologue: prime stage 0 with block 0.
    if (cnt > 0) {
        const int n0 = list[0];
        LOAD_BLOCK(sb, n0, __ldg(&bcols[n0]));
    }
    CP_COMMIT();
    int pf_n = (cnt > 1) ? list[1] : 0;
    int pf_c = (cnt > 1) ? __ldg(&bcols[pf_n]) : 0;

    for (int i = 0; i < cnt; i++) {
        CP_WAIT(0);
        __syncthreads();

        // Prefetch block i+1 into the stage freed by iteration i-1.
        if (i + 1 < cnt) {
            LOAD_BLOCK(sb + ((i + 1) & 1) * STAGE, pf_n, pf_c);
            if (i + 2 < cnt) {
                pf_n = list[i + 2];
                pf_c = __ldg(&bcols[pf_n]);
            }
        }
        CP_COMMIT();

        const uint32_t xs = sb + (i & 1) * STAGE;

        #pragma unroll
        for (int kc = 0; kc < 4; kc++) {
            uint32_t ah[2][4], bh[2][4];
            #pragma unroll
            for (int mi = 0; mi < 2; mi++)
                ldsm_x4(ah[mi], xs + aoff[mi] + kc * 32);
            #pragma unroll
            for (int j2 = 0; j2 < 2; j2++)
                ldsm_x4(bh[j2], xs + boff[j2] + kc * 32);
            #pragma unroll
            for (int mi = 0; mi < 2; mi++)
                #pragma unroll
                for (int j2 = 0; j2 < 2; j2++) {
                    mma_f16(acc[mi][2 * j2 + 0], ah[mi], bh[j2][0], bh[j2][1]);
                    mma_f16(acc[mi][2 * j2 + 1], ah[mi], bh[j2][2], bh[j2][3]);
                }
        }
    }

    // Epilogue: bias + tanh-GELU, float2 stores.
    const int row0 = lane >> 2;
    const int cp2  = (lane & 3) * 2;
    #pragma unroll
    for (int mi = 0; mi < 2; mi++) {
        #pragma unroll
        for (int nj = 0; nj < 4; nj++) {
            const int nb = wn + nj * 8 + cp2;
            const float b0 = __ldg(&bias[r * 64 + nb]);
            const float b1 = __ldg(&bias[r * 64 + nb + 1]);
            #pragma unroll
            for (int h = 0; h < 2; h++) {
                const int m = wt + mi * 16 + row0 + h * 8;
                float2 o;
                o.x = gelu_tanh(acc[mi][nj][2 * h + 0] + b0);
                o.y = gelu_tanh(acc[mi][nj][2 * h + 1] + b1);
                *(float2*)&out[(size_t)(t0 + m) * MDIM + r * 64 + nb] = o;
            }
        }
    }
#undef LOAD_BLOCK
}

// ---------------------------------------------------------------------------
extern "C" void kernel_launch(void* const* d_in, const int* in_sizes, int n_in,
                              void* d_out, int out_size)
{
    const float* x      = (const float*)d_in[0];
    const float* values = (const float*)d_in[1];
    const float* bias   = (const float*)d_in[2];
    const int*   brows  = (const int*)d_in[3];
    const int*   bcols  = (const int*)d_in[4];
    float*       out    = (float*)d_out;

    const int n_blocks = in_sizes[3];
    const int x_elems  = in_sizes[0];
    const int v_elems  = in_sizes[1];

    cudaFuncSetAttribute(fsl_hmma_kernel,
                         cudaFuncAttributeMaxDynamicSharedMemorySize, SMEM_TOTAL);

    prepass_kernel<<<LBLK + XBLK + VBLK, 256>>>(x, values, brows,
                                                x_elems / 4, v_elems / 4, n_blocks);

    fsl_hmma_kernel<<<1024, 256, SMEM_TOTAL>>>(bias, bcols, out);
}